// round 2
// baseline (speedup 1.0000x reference)
#include <cuda_runtime.h>
#include <math.h>

#define BB 2
#define SS 2048
#define DD 1024
#define HH 16
#define DP 64
#define MM (BB * SS)   // 4096

// Scratch (allocation-free rule: __device__ globals)
__device__ float g_q[MM * DD];
__device__ float g_k[MM * DD];
__device__ float g_v[MM * DD];
__device__ float g_c[MM * DD];

// ---------------------------------------------------------------------------
// Generic tiled SGEMM with bias: C[M,N] = A[M,K] @ W[K,N] + bias[N]
// 64x64 output tile, K-tile 16, 16x16 threads, 4x4 micro-tile per thread.
// ---------------------------------------------------------------------------
__global__ void sgemm_bias(const float* __restrict__ A,
                           const float* __restrict__ W,
                           const float* __restrict__ bias,
                           float* __restrict__ C,
                           int Mdim, int Ndim, int Kdim) {
    __shared__ float As[16][65];   // As[kk][m]
    __shared__ float Bs[16][65];   // Bs[kk][n]

    const int tx = threadIdx.x, ty = threadIdx.y;
    const int tid = ty * 16 + tx;
    const int n0 = blockIdx.x * 64;
    const int m0 = blockIdx.y * 64;

    float acc[4][4] = {};

    for (int k0 = 0; k0 < Kdim; k0 += 16) {
        // Load A tile (64 m x 16 k), store transposed As[kk][m]
        #pragma unroll
        for (int idx = tid; idx < 64 * 16; idx += 256) {
            int m = idx >> 4, kk = idx & 15;
            As[kk][m] = A[(size_t)(m0 + m) * Kdim + k0 + kk];
        }
        // Load W tile (16 k x 64 n)
        #pragma unroll
        for (int idx = tid; idx < 16 * 64; idx += 256) {
            int kk = idx >> 6, n = idx & 63;
            Bs[kk][n] = W[(size_t)(k0 + kk) * Ndim + n0 + n];
        }
        __syncthreads();

        #pragma unroll
        for (int kk = 0; kk < 16; kk++) {
            float a[4], b[4];
            #pragma unroll
            for (int i = 0; i < 4; i++) a[i] = As[kk][ty + 16 * i];
            #pragma unroll
            for (int j = 0; j < 4; j++) b[j] = Bs[kk][tx + 16 * j];
            #pragma unroll
            for (int i = 0; i < 4; i++)
                #pragma unroll
                for (int j = 0; j < 4; j++)
                    acc[i][j] = fmaf(a[i], b[j], acc[i][j]);
        }
        __syncthreads();
    }

    #pragma unroll
    for (int i = 0; i < 4; i++) {
        int m = m0 + ty + 16 * i;
        #pragma unroll
        for (int j = 0; j < 4; j++) {
            int n = n0 + tx + 16 * j;
            C[(size_t)m * Ndim + n] = acc[i][j] + bias[n];
        }
    }
}

// ---------------------------------------------------------------------------
// Attention scores: logits[z, q, k] = scale * dot(Qh[q,:], Kh[k,:]) + mask*-1e9
// z = b*H + h. 64x64 output tile per block, depth=64 fully in smem.
// ---------------------------------------------------------------------------
__global__ void attn_scores(const float* __restrict__ Q,
                            const float* __restrict__ K,
                            const float* __restrict__ mask,
                            float* __restrict__ attn) {
    __shared__ float Qs[64][65];
    __shared__ float Ks[64][65];

    const int z = blockIdx.z;
    const int b = z / HH;
    const int h = z % HH;
    const int q0 = blockIdx.y * 64;
    const int k0 = blockIdx.x * 64;
    const int tx = threadIdx.x, ty = threadIdx.y;
    const int tid = ty * 16 + tx;

    const float* Qb = Q + (size_t)(b * SS + q0) * DD + h * DP;
    const float* Kb = K + (size_t)(b * SS + k0) * DD + h * DP;

    #pragma unroll
    for (int idx = tid; idx < 64 * 64; idx += 256) {
        int r = idx >> 6, c = idx & 63;
        Qs[r][c] = Qb[(size_t)r * DD + c];
        Ks[r][c] = Kb[(size_t)r * DD + c];
    }
    __syncthreads();

    float acc[4][4] = {};
    #pragma unroll
    for (int d = 0; d < 64; d++) {
        float a[4], bb[4];
        #pragma unroll
        for (int i = 0; i < 4; i++) a[i] = Qs[ty + 16 * i][d];
        #pragma unroll
        for (int j = 0; j < 4; j++) bb[j] = Ks[tx + 16 * j][d];
        #pragma unroll
        for (int i = 0; i < 4; i++)
            #pragma unroll
            for (int j = 0; j < 4; j++)
                acc[i][j] = fmaf(a[i], bb[j], acc[i][j]);
    }

    const float scale = 0.125f;  // 1/sqrt(64)
    #pragma unroll
    for (int i = 0; i < 4; i++) {
        int qi = q0 + ty + 16 * i;
        #pragma unroll
        for (int j = 0; j < 4; j++) {
            int kj = k0 + tx + 16 * j;
            float val = acc[i][j] * scale + mask[b * SS + kj] * (-1e9f);
            attn[((size_t)z * SS + qi) * SS + kj] = val;
        }
    }
}

// ---------------------------------------------------------------------------
// Row softmax in place. One block of 256 threads per row of length 2048.
// ---------------------------------------------------------------------------
__global__ void softmax_rows(float* __restrict__ attn) {
    const int row = blockIdx.x;
    float* p = attn + (size_t)row * SS;
    const int t = threadIdx.x;

    __shared__ float red[256];

    float v[8];
    float mx = -INFINITY;
    #pragma unroll
    for (int i = 0; i < 8; i++) {
        v[i] = p[t + i * 256];
        mx = fmaxf(mx, v[i]);
    }
    red[t] = mx;
    __syncthreads();
    for (int s = 128; s > 0; s >>= 1) {
        if (t < s) red[t] = fmaxf(red[t], red[t + s]);
        __syncthreads();
    }
    mx = red[0];
    __syncthreads();

    float sum = 0.f;
    #pragma unroll
    for (int i = 0; i < 8; i++) {
        v[i] = __expf(v[i] - mx);
        sum += v[i];
    }
    red[t] = sum;
    __syncthreads();
    for (int s = 128; s > 0; s >>= 1) {
        if (t < s) red[t] += red[t + s];
        __syncthreads();
    }
    sum = red[0];

    const float inv = 1.0f / sum;
    #pragma unroll
    for (int i = 0; i < 8; i++) p[t + i * 256] = v[i] * inv;
}

// ---------------------------------------------------------------------------
// ctx = attn @ Vh : per z=(b,h), [2048,2048] @ [2048,64] -> [2048,64].
// Block handles 64 q-rows x 64 d-cols (all of depth); K loop in chunks of 32.
// ---------------------------------------------------------------------------
__global__ void attn_av(const float* __restrict__ attn,
                        const float* __restrict__ V,
                        float* __restrict__ C) {
    __shared__ float As[64][33];   // attn tile: 64 q x 32 k
    __shared__ float Vs[32][65];   // V tile:    32 k x 64 d

    const int z = blockIdx.y;
    const int b = z / HH;
    const int h = z % HH;
    const int q0 = blockIdx.x * 64;
    const int tx = threadIdx.x, ty = threadIdx.y;
    const int tid = ty * 16 + tx;

    float acc[4][4] = {};

    for (int k0 = 0; k0 < SS; k0 += 32) {
        #pragma unroll
        for (int idx = tid; idx < 64 * 32; idx += 256) {
            int r = idx >> 5, c = idx & 31;
            As[r][c] = attn[((size_t)z * SS + q0 + r) * SS + k0 + c];
        }
        #pragma unroll
        for (int idx = tid; idx < 32 * 64; idx += 256) {
            int r = idx >> 6, c = idx & 63;
            Vs[r][c] = V[(size_t)(b * SS + k0 + r) * DD + h * DP + c];
        }
        __syncthreads();

        #pragma unroll
        for (int kk = 0; kk < 32; kk++) {
            float a[4], bb[4];
            #pragma unroll
            for (int i = 0; i < 4; i++) a[i] = As[ty + 16 * i][kk];
            #pragma unroll
            for (int j = 0; j < 4; j++) bb[j] = Vs[kk][tx + 16 * j];
            #pragma unroll
            for (int i = 0; i < 4; i++)
                #pragma unroll
                for (int j = 0; j < 4; j++)
                    acc[i][j] = fmaf(a[i], bb[j], acc[i][j]);
        }
        __syncthreads();
    }

    #pragma unroll
    for (int i = 0; i < 4; i++) {
        int qi = q0 + ty + 16 * i;
        #pragma unroll
        for (int j = 0; j < 4; j++) {
            int dj = tx + 16 * j;
            C[(size_t)(b * SS + qi) * DD + h * DP + dj] = acc[i][j];
        }
    }
}

// ---------------------------------------------------------------------------
extern "C" void kernel_launch(void* const* d_in, const int* in_sizes, int n_in,
                              void* d_out, int out_size) {
    const float* q    = (const float*)d_in[0];
    const float* k    = (const float*)d_in[1];
    const float* v    = (const float*)d_in[2];
    const float* mask = (const float*)d_in[3];
    const float* Wq   = (const float*)d_in[4];
    const float* bq   = (const float*)d_in[5];
    const float* Wk   = (const float*)d_in[6];
    const float* bk   = (const float*)d_in[7];
    const float* Wv   = (const float*)d_in[8];
    const float* bv   = (const float*)d_in[9];
    const float* Wo   = (const float*)d_in[10];
    const float* bo   = (const float*)d_in[11];

    float* out  = (float*)d_out;
    float* attn = out + (size_t)MM * DD;   // output layout: (out, attn)

    float *pq, *pk, *pv, *pc;
    cudaGetSymbolAddress((void**)&pq, g_q);
    cudaGetSymbolAddress((void**)&pk, g_k);
    cudaGetSymbolAddress((void**)&pv, g_v);
    cudaGetSymbolAddress((void**)&pc, g_c);

    dim3 thr(16, 16);
    dim3 gProj(DD / 64, MM / 64);             // (16, 64)

    sgemm_bias<<<gProj, thr>>>(q, Wq, bq, pq, MM, DD, DD);
    sgemm_bias<<<gProj, thr>>>(k, Wk, bk, pk, MM, DD, DD);
    sgemm_bias<<<gProj, thr>>>(v, Wv, bv, pv, MM, DD, DD);

    dim3 gScores(SS / 64, SS / 64, BB * HH);  // (32, 32, 32)
    attn_scores<<<gScores, thr>>>(pq, pk, mask, attn);

    softmax_rows<<<BB * HH * SS, 256>>>(attn);

    dim3 gAV(SS / 64, BB * HH);               // (32, 32)
    attn_av<<<gAV, thr>>>(attn, pv, pc);

    sgemm_bias<<<gProj, thr>>>(pc, Wo, bo, out, MM, DD, DD);
}

// round 3
// speedup vs baseline: 2.7195x; 2.7195x over previous
#include <cuda_runtime.h>
#include <math.h>

#define BB 2
#define SS 2048
#define DD 1024
#define HH 16
#define DP 64
#define MM (BB * SS)   // 4096

// Scratch (allocation-free rule: __device__ globals)
__device__ float g_q[MM * DD];
__device__ float g_k[MM * DD];
__device__ float g_v[MM * DD];
__device__ float g_c[MM * DD];

// ---------------------------------------------------------------------------
// Helpers: tf32 convert + m16n8k8 tf32 MMA
// ---------------------------------------------------------------------------
__device__ __forceinline__ unsigned f2tf(float x) {
    unsigned r;
    asm("cvt.rna.tf32.f32 %0, %1;" : "=r"(r) : "f"(x));
    return r;
}

__device__ __forceinline__ void mma8(float* c, const unsigned* a, const unsigned* b) {
    asm volatile(
        "mma.sync.aligned.m16n8k8.row.col.f32.tf32.tf32.f32 "
        "{%0,%1,%2,%3}, {%4,%5,%6,%7}, {%8,%9}, {%0,%1,%2,%3};"
        : "+f"(c[0]), "+f"(c[1]), "+f"(c[2]), "+f"(c[3])
        : "r"(a[0]), "r"(a[1]), "r"(a[2]), "r"(a[3]), "r"(b[0]), "r"(b[1]));
}

// ---------------------------------------------------------------------------
// Tensor-core SGEMM + bias: C[M,N] = A[M,K] @ W[K,N] + bias[N]
// Block 256 thr, tile 128x128, K-tile 32. 8 warps in 4x2, warp tile 32x64.
// As[m][k] stride 36 (bank = 4g+t), Bs[k][n] stride 136 (bank = 8t+g).
// ---------------------------------------------------------------------------
#define AS_STR 36
#define BS_STR 136
__global__ void sgemm_bias_tc(const float* __restrict__ A,
                              const float* __restrict__ W,
                              const float* __restrict__ bias,
                              float* __restrict__ C,
                              int Mdim, int Ndim, int Kdim) {
    __shared__ unsigned As[128 * AS_STR];
    __shared__ unsigned Bs[32 * BS_STR];

    const int tid = threadIdx.x;
    const int warp = tid >> 5, lane = tid & 31;
    const int g = lane >> 2, t = lane & 3;
    const int wm = warp >> 1, wn = warp & 1;
    const int m0 = blockIdx.y * 128, n0 = blockIdx.x * 128;

    float acc[2][8][4] = {};

    for (int k0 = 0; k0 < Kdim; k0 += 32) {
        // A tile: 128 x 32 -> 1024 float4
        #pragma unroll
        for (int i = tid; i < 1024; i += 256) {
            int r = i >> 3, c4 = (i & 7) * 4;
            float4 v = *(const float4*)(A + (size_t)(m0 + r) * Kdim + k0 + c4);
            As[r * AS_STR + c4 + 0] = f2tf(v.x);
            As[r * AS_STR + c4 + 1] = f2tf(v.y);
            As[r * AS_STR + c4 + 2] = f2tf(v.z);
            As[r * AS_STR + c4 + 3] = f2tf(v.w);
        }
        // B tile: 32 x 128 -> 1024 float4
        #pragma unroll
        for (int i = tid; i < 1024; i += 256) {
            int r = i >> 5, c4 = (i & 31) * 4;
            float4 v = *(const float4*)(W + (size_t)(k0 + r) * Ndim + n0 + c4);
            Bs[r * BS_STR + c4 + 0] = f2tf(v.x);
            Bs[r * BS_STR + c4 + 1] = f2tf(v.y);
            Bs[r * BS_STR + c4 + 2] = f2tf(v.z);
            Bs[r * BS_STR + c4 + 3] = f2tf(v.w);
        }
        __syncthreads();

        #pragma unroll
        for (int k = 0; k < 32; k += 8) {
            unsigned a[2][4], bfr[8][2];
            #pragma unroll
            for (int mt = 0; mt < 2; mt++) {
                int m = wm * 32 + mt * 16;
                a[mt][0] = As[(m + g) * AS_STR + k + t];
                a[mt][1] = As[(m + g + 8) * AS_STR + k + t];
                a[mt][2] = As[(m + g) * AS_STR + k + t + 4];
                a[mt][3] = As[(m + g + 8) * AS_STR + k + t + 4];
            }
            #pragma unroll
            for (int nt = 0; nt < 8; nt++) {
                int n = wn * 64 + nt * 8 + g;
                bfr[nt][0] = Bs[(k + t) * BS_STR + n];
                bfr[nt][1] = Bs[(k + t + 4) * BS_STR + n];
            }
            #pragma unroll
            for (int mt = 0; mt < 2; mt++)
                #pragma unroll
                for (int nt = 0; nt < 8; nt++)
                    mma8(acc[mt][nt], a[mt], bfr[nt]);
        }
        __syncthreads();
    }

    #pragma unroll
    for (int mt = 0; mt < 2; mt++) {
        int row = m0 + wm * 32 + mt * 16 + g;
        #pragma unroll
        for (int nt = 0; nt < 8; nt++) {
            int col = n0 + wn * 64 + nt * 8 + 2 * t;
            float b0 = bias[col], b1 = bias[col + 1];
            C[(size_t)row * Ndim + col]           = acc[mt][nt][0] + b0;
            C[(size_t)row * Ndim + col + 1]       = acc[mt][nt][1] + b1;
            C[(size_t)(row + 8) * Ndim + col]     = acc[mt][nt][2] + b0;
            C[(size_t)(row + 8) * Ndim + col + 1] = acc[mt][nt][3] + b1;
        }
    }
}

// ---------------------------------------------------------------------------
// Attention scores (tensor core): logits[z,q,k] = 0.125*Qh[q,:]·Kh[k,:] - 1e9*mask
// Block: 128 q x 128 k, depth=64 entirely in smem. Both tiles [row][d] stride 68.
// ---------------------------------------------------------------------------
#define QS_STR 68
__global__ void attn_scores_tc(const float* __restrict__ Q,
                               const float* __restrict__ K,
                               const float* __restrict__ mask,
                               float* __restrict__ attn) {
    extern __shared__ unsigned sm[];
    unsigned* Qs = sm;                  // [128][68]
    unsigned* Ks = sm + 128 * QS_STR;   // [128][68]

    const int z = blockIdx.z;
    const int b = z >> 4;
    const int h = z & 15;
    const int q0 = blockIdx.y * 128, k0 = blockIdx.x * 128;
    const int tid = threadIdx.x;
    const int warp = tid >> 5, lane = tid & 31;
    const int g = lane >> 2, t = lane & 3;
    const int wm = warp >> 1, wn = warp & 1;

    const float* Qb = Q + (size_t)(b * SS + q0) * DD + h * DP;
    const float* Kb = K + (size_t)(b * SS + k0) * DD + h * DP;

    #pragma unroll
    for (int i = tid; i < 128 * 16; i += 256) {
        int r = i >> 4, c4 = (i & 15) * 4;
        float4 vq = *(const float4*)(Qb + (size_t)r * DD + c4);
        float4 vk = *(const float4*)(Kb + (size_t)r * DD + c4);
        Qs[r * QS_STR + c4 + 0] = f2tf(vq.x);
        Qs[r * QS_STR + c4 + 1] = f2tf(vq.y);
        Qs[r * QS_STR + c4 + 2] = f2tf(vq.z);
        Qs[r * QS_STR + c4 + 3] = f2tf(vq.w);
        Ks[r * QS_STR + c4 + 0] = f2tf(vk.x);
        Ks[r * QS_STR + c4 + 1] = f2tf(vk.y);
        Ks[r * QS_STR + c4 + 2] = f2tf(vk.z);
        Ks[r * QS_STR + c4 + 3] = f2tf(vk.w);
    }
    __syncthreads();

    float acc[2][8][4] = {};
    #pragma unroll
    for (int k = 0; k < 64; k += 8) {
        unsigned a[2][4], bfr[8][2];
        #pragma unroll
        for (int mt = 0; mt < 2; mt++) {
            int m = wm * 32 + mt * 16;
            a[mt][0] = Qs[(m + g) * QS_STR + k + t];
            a[mt][1] = Qs[(m + g + 8) * QS_STR + k + t];
            a[mt][2] = Qs[(m + g) * QS_STR + k + t + 4];
            a[mt][3] = Qs[(m + g + 8) * QS_STR + k + t + 4];
        }
        #pragma unroll
        for (int nt = 0; nt < 8; nt++) {
            int n = wn * 64 + nt * 8 + g;
            bfr[nt][0] = Ks[n * QS_STR + k + t];
            bfr[nt][1] = Ks[n * QS_STR + k + t + 4];
        }
        #pragma unroll
        for (int mt = 0; mt < 2; mt++)
            #pragma unroll
            for (int nt = 0; nt < 8; nt++)
                mma8(acc[mt][nt], a[mt], bfr[nt]);
    }

    #pragma unroll
    for (int mt = 0; mt < 2; mt++) {
        int qi = q0 + wm * 32 + mt * 16 + g;
        size_t base0 = ((size_t)z * SS + qi) * SS;
        size_t base1 = ((size_t)z * SS + qi + 8) * SS;
        #pragma unroll
        for (int nt = 0; nt < 8; nt++) {
            int kj = k0 + wn * 64 + nt * 8 + 2 * t;
            float mk0 = mask[b * SS + kj] * (-1e9f);
            float mk1 = mask[b * SS + kj + 1] * (-1e9f);
            attn[base0 + kj]     = acc[mt][nt][0] * 0.125f + mk0;
            attn[base0 + kj + 1] = acc[mt][nt][1] * 0.125f + mk1;
            attn[base1 + kj]     = acc[mt][nt][2] * 0.125f + mk0;
            attn[base1 + kj + 1] = acc[mt][nt][3] * 0.125f + mk1;
        }
    }
}

// ---------------------------------------------------------------------------
// Row softmax, float4-vectorized. One 256-thread block per row of 2048.
// ---------------------------------------------------------------------------
__global__ void softmax_rows(float* __restrict__ attn) {
    const int row = blockIdx.x;
    float4* p = (float4*)(attn + (size_t)row * SS);
    const int tt = threadIdx.x;
    const int lane = tt & 31, warp = tt >> 5;

    __shared__ float red[8];

    float4 v0 = p[tt], v1 = p[tt + 256];
    float mx = fmaxf(fmaxf(fmaxf(v0.x, v0.y), fmaxf(v0.z, v0.w)),
                     fmaxf(fmaxf(v1.x, v1.y), fmaxf(v1.z, v1.w)));
    #pragma unroll
    for (int o = 16; o; o >>= 1) mx = fmaxf(mx, __shfl_xor_sync(~0u, mx, o));
    if (lane == 0) red[warp] = mx;
    __syncthreads();
    mx = red[0];
    #pragma unroll
    for (int i = 1; i < 8; i++) mx = fmaxf(mx, red[i]);
    __syncthreads();

    v0.x = __expf(v0.x - mx); v0.y = __expf(v0.y - mx);
    v0.z = __expf(v0.z - mx); v0.w = __expf(v0.w - mx);
    v1.x = __expf(v1.x - mx); v1.y = __expf(v1.y - mx);
    v1.z = __expf(v1.z - mx); v1.w = __expf(v1.w - mx);
    float sum = v0.x + v0.y + v0.z + v0.w + v1.x + v1.y + v1.z + v1.w;
    #pragma unroll
    for (int o = 16; o; o >>= 1) sum += __shfl_xor_sync(~0u, sum, o);
    if (lane == 0) red[warp] = sum;
    __syncthreads();
    sum = red[0];
    #pragma unroll
    for (int i = 1; i < 8; i++) sum += red[i];

    const float inv = 1.0f / sum;
    v0.x *= inv; v0.y *= inv; v0.z *= inv; v0.w *= inv;
    v1.x *= inv; v1.y *= inv; v1.z *= inv; v1.w *= inv;
    p[tt] = v0;
    p[tt + 256] = v1;
}

// ---------------------------------------------------------------------------
// ctx = attn @ Vh (tensor core). Per z: [2048,2048]@[2048,64].
// Block: 128 q x 64 d, K-tile 32. 8 warps 4x2, warp tile 32x32.
// ---------------------------------------------------------------------------
#define VS_STR 72
__global__ void attn_av_tc(const float* __restrict__ attn,
                           const float* __restrict__ V,
                           float* __restrict__ C) {
    __shared__ unsigned As[128 * AS_STR];
    __shared__ unsigned Vs[32 * VS_STR];

    const int z = blockIdx.y;
    const int b = z >> 4;
    const int h = z & 15;
    const int q0 = blockIdx.x * 128;
    const int tid = threadIdx.x;
    const int warp = tid >> 5, lane = tid & 31;
    const int g = lane >> 2, t = lane & 3;
    const int wm = warp >> 1, wn = warp & 1;

    float acc[2][4][4] = {};

    for (int k0 = 0; k0 < SS; k0 += 32) {
        #pragma unroll
        for (int i = tid; i < 1024; i += 256) {
            int r = i >> 3, c4 = (i & 7) * 4;
            float4 v = *(const float4*)(attn + ((size_t)z * SS + q0 + r) * SS + k0 + c4);
            As[r * AS_STR + c4 + 0] = f2tf(v.x);
            As[r * AS_STR + c4 + 1] = f2tf(v.y);
            As[r * AS_STR + c4 + 2] = f2tf(v.z);
            As[r * AS_STR + c4 + 3] = f2tf(v.w);
        }
        #pragma unroll
        for (int i = tid; i < 512; i += 256) {
            int r = i >> 4, c4 = (i & 15) * 4;
            float4 v = *(const float4*)(V + (size_t)(b * SS + k0 + r) * DD + h * DP + c4);
            Vs[r * VS_STR + c4 + 0] = f2tf(v.x);
            Vs[r * VS_STR + c4 + 1] = f2tf(v.y);
            Vs[r * VS_STR + c4 + 2] = f2tf(v.z);
            Vs[r * VS_STR + c4 + 3] = f2tf(v.w);
        }
        __syncthreads();

        #pragma unroll
        for (int kk = 0; kk < 32; kk += 8) {
            unsigned a[2][4], bfr[4][2];
            #pragma unroll
            for (int mt = 0; mt < 2; mt++) {
                int m = wm * 32 + mt * 16;
                a[mt][0] = As[(m + g) * AS_STR + kk + t];
                a[mt][1] = As[(m + g + 8) * AS_STR + kk + t];
                a[mt][2] = As[(m + g) * AS_STR + kk + t + 4];
                a[mt][3] = As[(m + g + 8) * AS_STR + kk + t + 4];
            }
            #pragma unroll
            for (int nt = 0; nt < 4; nt++) {
                int n = wn * 32 + nt * 8 + g;
                bfr[nt][0] = Vs[(kk + t) * VS_STR + n];
                bfr[nt][1] = Vs[(kk + t + 4) * VS_STR + n];
            }
            #pragma unroll
            for (int mt = 0; mt < 2; mt++)
                #pragma unroll
                for (int nt = 0; nt < 4; nt++)
                    mma8(acc[mt][nt], a[mt], bfr[nt]);
        }
        __syncthreads();
    }

    #pragma unroll
    for (int mt = 0; mt < 2; mt++) {
        int qi = q0 + wm * 32 + mt * 16 + g;
        #pragma unroll
        for (int nt = 0; nt < 4; nt++) {
            int dj = wn * 32 + nt * 8 + 2 * t;
            size_t base0 = (size_t)(b * SS + qi) * DD + h * DP;
            size_t base1 = (size_t)(b * SS + qi + 8) * DD + h * DP;
            C[base0 + dj]     = acc[mt][nt][0];
            C[base0 + dj + 1] = acc[mt][nt][1];
            C[base1 + dj]     = acc[mt][nt][2];
            C[base1 + dj + 1] = acc[mt][nt][3];
        }
    }
}

// ---------------------------------------------------------------------------
extern "C" void kernel_launch(void* const* d_in, const int* in_sizes, int n_in,
                              void* d_out, int out_size) {
    const float* q    = (const float*)d_in[0];
    const float* k    = (const float*)d_in[1];
    const float* v    = (const float*)d_in[2];
    const float* mask = (const float*)d_in[3];
    const float* Wq   = (const float*)d_in[4];
    const float* bq   = (const float*)d_in[5];
    const float* Wk   = (const float*)d_in[6];
    const float* bk   = (const float*)d_in[7];
    const float* Wv   = (const float*)d_in[8];
    const float* bv   = (const float*)d_in[9];
    const float* Wo   = (const float*)d_in[10];
    const float* bo   = (const float*)d_in[11];

    float* out  = (float*)d_out;
    float* attn = out + (size_t)MM * DD;   // output layout: (out, attn)

    float *pq, *pk, *pv, *pc;
    cudaGetSymbolAddress((void**)&pq, g_q);
    cudaGetSymbolAddress((void**)&pk, g_k);
    cudaGetSymbolAddress((void**)&pv, g_v);
    cudaGetSymbolAddress((void**)&pc, g_c);

    static int smem_set = 0;
    const int scores_smem = 2 * 128 * QS_STR * 4;   // 69632 bytes
    if (!smem_set) {
        cudaFuncSetAttribute(attn_scores_tc,
                             cudaFuncAttributeMaxDynamicSharedMemorySize,
                             scores_smem);
        smem_set = 1;
    }

    dim3 gProj(DD / 128, MM / 128);                 // (8, 32)
    sgemm_bias_tc<<<gProj, 256>>>(q, Wq, bq, pq, MM, DD, DD);
    sgemm_bias_tc<<<gProj, 256>>>(k, Wk, bk, pk, MM, DD, DD);
    sgemm_bias_tc<<<gProj, 256>>>(v, Wv, bv, pv, MM, DD, DD);

    dim3 gScores(SS / 128, SS / 128, BB * HH);      // (16, 16, 32)
    attn_scores_tc<<<gScores, 256, scores_smem>>>(pq, pk, mask, attn);

    softmax_rows<<<BB * HH * SS, 256>>>(attn);

    dim3 gAV(SS / 128, BB * HH);                    // (16, 32)
    attn_av_tc<<<gAV, 256>>>(attn, pv, pc);

    sgemm_bias_tc<<<gProj, 256>>>(pc, Wo, bo, out, MM, DD, DD);
}